// round 1
// baseline (speedup 1.0000x reference)
#include <cuda_runtime.h>

// Discriminator neural-SDE scan.
// B=512, T=4096, D=8, H=16, W=16.
// One warp per batch element; 512 one-warp blocks.
// Weights register-resident per lane; y/h exchanged via tiny per-block SMEM;
// ys rows streamed through a 4-deep float4 register prefetch pipeline.

#define T_STEPS 4096
#define FULLMASK 0xffffffffu

__device__ __forceinline__ float dot16(const float* __restrict__ w,
                                       const float* __restrict__ v,
                                       float init) {
    float a0 = init, a1 = 0.f, a2 = 0.f, a3 = 0.f;
#pragma unroll
    for (int k = 0; k < 16; k += 4) {
        a0 = fmaf(w[k + 0], v[k + 0], a0);
        a1 = fmaf(w[k + 1], v[k + 1], a1);
        a2 = fmaf(w[k + 2], v[k + 2], a2);
        a3 = fmaf(w[k + 3], v[k + 3], a3);
    }
    return (a0 + a1) + (a2 + a3);
}

// tanh(x) = 1 - 2/(exp(2x)+1); branchless, handles saturation via inf/0.
__device__ __forceinline__ float tanh_acc(float x) {
    float e = expf(2.f * x);
    return 1.f - __fdividef(2.f, e + 1.f);
}

// lipswish(x) = 0.909 * x * sigmoid(x)
__device__ __forceinline__ float lipswish(float x) {
    return 0.909f * __fdividef(x, 1.f + expf(-x));
}

__global__ void __launch_bounds__(32) sde_scan_kernel(
    const float* __restrict__ ts, const float* __restrict__ ys,
    const float* __restrict__ iW1, const float* __restrict__ ib1,
    const float* __restrict__ iW2, const float* __restrict__ ib2,
    const float* __restrict__ vW1, const float* __restrict__ vb1,
    const float* __restrict__ vW2, const float* __restrict__ vb2,
    const float* __restrict__ cW1, const float* __restrict__ cb1,
    const float* __restrict__ cW2, const float* __restrict__ cb2,
    const float* __restrict__ rW, const float* __restrict__ rb,
    float* __restrict__ out)
{
    const int b = blockIdx.x;
    const int lane = threadIdx.x & 31;
    __shared__ __align__(16) float s_y[16];
    __shared__ __align__(16) float s_h[32];

    const float t0 = ts[0];
    const float* __restrict__ ysb = ys + (size_t)b * (T_STEPS * 8);

    // ---- load weights into registers ----
    // W1: lanes 0-15 hold vW1 rows, lanes 16-31 hold cW1 rows. Row = [t-coef, 16 y-coefs].
    float w1t, w1[16], b1;
    {
        const float* W  = (lane < 16) ? (vW1 + lane * 17) : (cW1 + (lane - 16) * 17);
        w1t = W[0];
#pragma unroll
        for (int k = 0; k < 16; k++) w1[k] = W[1 + k];
        b1 = (lane < 16) ? vb1[lane] : cb1[lane - 16];
    }
    // cW2: lane l holds rows 4l..4l+3 (flat index = h*8+d).
    float cw2[4][16], cb2r[4];
#pragma unroll
    for (int j = 0; j < 4; j++) {
        const int fl = lane * 4 + j;
        cb2r[j] = cb2[fl];
#pragma unroll
        for (int k = 0; k < 16; k++) cw2[j][k] = cW2[fl * 16 + k];
    }
    // vW2: lanes 0-15 hold row l.
    float vw2[16], vb2r = 0.f;
    if (lane < 16) {
        vb2r = vb2[lane];
#pragma unroll
        for (int k = 0; k < 16; k++) vw2[k] = vW2[lane * 16 + k];
    }

    // ---- initial MLP: y0 = relu([t0, ys[b,0]] @ iW1^T + ib1) @ iW2^T + ib2 ----
    if (lane < 16) {
        float a = fmaf(iW1[lane * 9], t0, ib1[lane]);
#pragma unroll
        for (int k = 0; k < 8; k++) a = fmaf(iW1[lane * 9 + 1 + k], ysb[k], a);
        s_h[lane] = fmaxf(a, 0.f);
    }
    __syncwarp();
    if (lane < 16) {
        float a = ib2[lane];
#pragma unroll
        for (int k = 0; k < 16; k++) a = fmaf(iW2[lane * 16 + k], s_h[k], a);
        s_y[lane] = a;
    }
    __syncwarp();
    if (lane == 0) {
        float a = rb[0];
#pragma unroll
        for (int k = 0; k < 16; k++) a = fmaf(rW[k], s_y[k], a);
        out[b * 2 + 0] = a;
    }
    __syncwarp();

    // ---- ys row loads: even lanes take d=0..3, odd lanes d=4..7 (one 32B sector/warp) ----
    const int d0 = (lane & 1) * 4;
    auto ldrow = [&](int r) -> float4 {
        return *reinterpret_cast<const float4*>(ysb + (size_t)r * 8 + d0);
    };

    // ---- one Euler step: y += f(z) + g(z)·dx ----
    auto step = [&](int n, const float4 pv, const float4 cv) {
        const float t = t0 + (float)n;

        // phase 1: hidden = lipswish(W1 @ [t, y] + b1)  (lane -> one hidden unit)
        float yv[16];
        {
            const float4* yq = reinterpret_cast<const float4*>(s_y);
            float4 q0 = yq[0], q1 = yq[1], q2 = yq[2], q3 = yq[3];
            yv[0]=q0.x;  yv[1]=q0.y;  yv[2]=q0.z;  yv[3]=q0.w;
            yv[4]=q1.x;  yv[5]=q1.y;  yv[6]=q1.z;  yv[7]=q1.w;
            yv[8]=q2.x;  yv[9]=q2.y;  yv[10]=q2.z; yv[11]=q2.w;
            yv[12]=q3.x; yv[13]=q3.y; yv[14]=q3.z; yv[15]=q3.w;
        }
        float h = dot16(w1, yv, fmaf(w1t, t, b1));
        s_h[lane] = lipswish(h);
        __syncwarp();

        // phase 2: g rows (all lanes, 4 each) from hc = s_h[16..31]
        float hcv[16];
        {
            const float4* hq = reinterpret_cast<const float4*>(s_h);
            float4 q0 = hq[4], q1 = hq[5], q2 = hq[6], q3 = hq[7];
            hcv[0]=q0.x;  hcv[1]=q0.y;  hcv[2]=q0.z;  hcv[3]=q0.w;
            hcv[4]=q1.x;  hcv[5]=q1.y;  hcv[6]=q1.z;  hcv[7]=q1.w;
            hcv[8]=q2.x;  hcv[9]=q2.y;  hcv[10]=q2.z; hcv[11]=q2.w;
            hcv[12]=q3.x; hcv[13]=q3.y; hcv[14]=q3.z; hcv[15]=q3.w;
        }
        float g[4];
#pragma unroll
        for (int j = 0; j < 4; j++)
            g[j] = tanh_acc(dot16(cw2[j], hcv, cb2r[j]));

        // f (lanes 0-15) from hv = s_h[0..15]
        float fv = 0.f;
        if (lane < 16) {
            float hvv[16];
            const float4* hq = reinterpret_cast<const float4*>(s_h);
            float4 q0 = hq[0], q1 = hq[1], q2 = hq[2], q3 = hq[3];
            hvv[0]=q0.x;  hvv[1]=q0.y;  hvv[2]=q0.z;  hvv[3]=q0.w;
            hvv[4]=q1.x;  hvv[5]=q1.y;  hvv[6]=q1.z;  hvv[7]=q1.w;
            hvv[8]=q2.x;  hvv[9]=q2.y;  hvv[10]=q2.z; hvv[11]=q2.w;
            hvv[12]=q3.x; hvv[13]=q3.y; hvv[14]=q3.z; hvv[15]=q3.w;
            fv = tanh_acc(dot16(vw2, hvv, vb2r));
        }

        // einsum: lane covers flat g idx 4l..4l+3 -> h = l>>1, d = d0..d0+3
        float4 dx;
        dx.x = cv.x - pv.x; dx.y = cv.y - pv.y;
        dx.z = cv.z - pv.z; dx.w = cv.w - pv.w;
        float part = g[0] * dx.x;
        part = fmaf(g[1], dx.y, part);
        part = fmaf(g[2], dx.z, part);
        part = fmaf(g[3], dx.w, part);
        part += __shfl_xor_sync(FULLMASK, part, 1);      // sum d-halves of h
        float fh = __shfl_sync(FULLMASK, fv, lane >> 1); // f[h] from lane h

        if (!(lane & 1)) {
            s_y[lane >> 1] += fh + part;
        }
        __syncwarp();
    };

    // ---- main loop: 4-step bodies with register-rotated row prefetch ----
    float4 rA = ldrow(0), rB = ldrow(1), rC = ldrow(2), rD = ldrow(3);
    int n = 0;
#pragma unroll 1
    for (int it = 0; it < 1023; it++) {   // n = 0..4091, prefetch rows n+4..n+7 <= 4095
        float4 p0 = ldrow(n + 4);
        step(n + 0, rA, rB);
        float4 p1 = ldrow(n + 5);
        step(n + 1, rB, rC);
        float4 p2 = ldrow(n + 6);
        step(n + 2, rC, rD);
        float4 p3 = ldrow(n + 7);
        step(n + 3, rD, p0);
        rA = p0; rB = p1; rC = p2; rD = p3;
        n += 4;
    }
    // tail: n = 4092, 4093, 4094 (rows 4092..4095 already resident)
    step(n + 0, rA, rB);
    step(n + 1, rB, rC);
    step(n + 2, rC, rD);

    // ---- readout of yT ----
    if (lane == 0) {
        float a = rb[0];
#pragma unroll
        for (int k = 0; k < 16; k++) a = fmaf(rW[k], s_y[k], a);
        out[b * 2 + 1] = a;
    }
}

extern "C" void kernel_launch(void* const* d_in, const int* in_sizes, int n_in,
                              void* d_out, int out_size) {
    const float* ts  = (const float*)d_in[0];
    const float* ys  = (const float*)d_in[1];
    const float* iW1 = (const float*)d_in[2];
    const float* ib1 = (const float*)d_in[3];
    const float* iW2 = (const float*)d_in[4];
    const float* ib2 = (const float*)d_in[5];
    const float* vW1 = (const float*)d_in[6];
    const float* vb1 = (const float*)d_in[7];
    const float* vW2 = (const float*)d_in[8];
    const float* vb2 = (const float*)d_in[9];
    const float* cW1 = (const float*)d_in[10];
    const float* cb1 = (const float*)d_in[11];
    const float* cW2 = (const float*)d_in[12];
    const float* cb2 = (const float*)d_in[13];
    const float* rW  = (const float*)d_in[14];
    const float* rb  = (const float*)d_in[15];

    const int Bn = out_size / 2;  // (B, 2, 1) float32
    sde_scan_kernel<<<Bn, 32>>>(ts, ys, iW1, ib1, iW2, ib2,
                                vW1, vb1, vW2, vb2,
                                cW1, cb1, cW2, cb2, rW, rb,
                                (float*)d_out);
}

// round 2
// speedup vs baseline: 1.0841x; 1.0841x over previous
#include <cuda_runtime.h>

// Discriminator neural-SDE scan. B=512, T=4096, D=8, H=16, W=16.
// One warp per batch element; 512 one-warp blocks.
// All state register-resident: y[16] replicated across lanes; h exchanged via
// SHFL (no SMEM, no __syncwarp in the main loop). ys rows streamed through a
// 4-deep float4 register prefetch pipeline. Fast EX2-based activations.

#define T_STEPS 4096
#define FULLMASK 0xffffffffu

__device__ __forceinline__ float dot16(const float* __restrict__ w,
                                       const float* __restrict__ v,
                                       float init) {
    float a0 = init, a1 = 0.f, a2 = 0.f, a3 = 0.f;
#pragma unroll
    for (int k = 0; k < 16; k += 4) {
        a0 = fmaf(w[k + 0], v[k + 0], a0);
        a1 = fmaf(w[k + 1], v[k + 1], a1);
        a2 = fmaf(w[k + 2], v[k + 2], a2);
        a3 = fmaf(w[k + 3], v[k + 3], a3);
    }
    return (a0 + a1) + (a2 + a3);
}

// tanh(x) = 1 - 2/(exp(2x)+1); EX2-based, branchless, saturates via inf/0.
__device__ __forceinline__ float tanh_fast(float x) {
    float e = __expf(2.f * x);
    return 1.f - __fdividef(2.f, e + 1.f);
}

// lipswish(x) = 0.909 * x * sigmoid(x), EX2-based.
__device__ __forceinline__ float lipswish_fast(float x) {
    return 0.909f * x * __fdividef(1.f, 1.f + __expf(-x));
}

__global__ void __launch_bounds__(32) sde_scan_kernel(
    const float* __restrict__ ts, const float* __restrict__ ys,
    const float* __restrict__ iW1, const float* __restrict__ ib1,
    const float* __restrict__ iW2, const float* __restrict__ ib2,
    const float* __restrict__ vW1, const float* __restrict__ vb1,
    const float* __restrict__ vW2, const float* __restrict__ vb2,
    const float* __restrict__ cW1, const float* __restrict__ cb1,
    const float* __restrict__ cW2, const float* __restrict__ cb2,
    const float* __restrict__ rW, const float* __restrict__ rb,
    float* __restrict__ out)
{
    const int b = blockIdx.x;
    const int lane = threadIdx.x & 31;

    const float t0 = ts[0];
    const float* __restrict__ ysb = ys + (size_t)b * (T_STEPS * 8);

    // ---- load weights into registers ----
    // W1: lanes 0-15 hold vW1 rows, lanes 16-31 hold cW1 rows. Row = [t-coef, 16 y-coefs].
    float w1t, w1[16], b1;
    {
        const float* W  = (lane < 16) ? (vW1 + lane * 17) : (cW1 + (lane - 16) * 17);
        w1t = W[0];
#pragma unroll
        for (int k = 0; k < 16; k++) w1[k] = W[1 + k];
        b1 = (lane < 16) ? vb1[lane] : cb1[lane - 16];
    }
    // cW2: lane l holds flat rows 4l..4l+3 (flat = h*8+d -> h = l>>1, d = (l&1)*4 + j).
    float cw2[4][16], cb2r[4];
#pragma unroll
    for (int j = 0; j < 4; j++) {
        const int fl = lane * 4 + j;
        cb2r[j] = cb2[fl];
#pragma unroll
        for (int k = 0; k < 16; k++) cw2[j][k] = cW2[fl * 16 + k];
    }
    // vW2: lanes 0-15 hold row `lane`; lanes 16-31 hold zeros (computed but unused).
    float vw2[16], vb2r = 0.f;
#pragma unroll
    for (int k = 0; k < 16; k++) vw2[k] = 0.f;
    if (lane < 16) {
        vb2r = vb2[lane];
#pragma unroll
        for (int k = 0; k < 16; k++) vw2[k] = vW2[lane * 16 + k];
    }

    // ---- initial MLP: y0 = relu([t0, ys[b,0]] @ iW1^T + ib1) @ iW2^T + ib2 ----
    float yv[16];
    {
        float a = 0.f;
        if (lane < 16) {
            a = fmaf(iW1[lane * 9], t0, ib1[lane]);
#pragma unroll
            for (int k = 0; k < 8; k++) a = fmaf(iW1[lane * 9 + 1 + k], ysb[k], a);
            a = fmaxf(a, 0.f);
        }
        float hv[16];
#pragma unroll
        for (int k = 0; k < 16; k++) hv[k] = __shfl_sync(FULLMASK, a, k);
        float y0 = 0.f;
        if (lane < 16) {
            y0 = ib2[lane];
#pragma unroll
            for (int k = 0; k < 16; k++) y0 = fmaf(iW2[lane * 16 + k], hv[k], y0);
        }
#pragma unroll
        for (int k = 0; k < 16; k++) yv[k] = __shfl_sync(FULLMASK, y0, k);
    }
    if (lane == 0) {
        float a = rb[0];
#pragma unroll
        for (int k = 0; k < 16; k++) a = fmaf(rW[k], yv[k], a);
        out[b * 2 + 0] = a;
    }

    // ---- ys row loads: even lanes d=0..3, odd lanes d=4..7 (one 64B sector pair/warp) ----
    const int d0 = (lane & 1) * 4;
    auto ldrow = [&](int r) -> float4 {
        return *reinterpret_cast<const float4*>(ysb + (size_t)r * 8 + d0);
    };

    float tf = t0;  // running t, avoids I2F on the chain head

    // ---- one Euler step: y += f(z) + g(z)·dx ; fully shfl-based ----
    auto step = [&](const float4 pv, const float4 cv) {
        // phase 1: h = lipswish(W1 @ [t, y] + b1)  (lane -> one hidden unit)
        float hact = lipswish_fast(dot16(w1, yv, fmaf(w1t, tf, b1)));
        tf += 1.f;

        // broadcast both halves of h to all lanes
        float hcv[16], hvv[16];
#pragma unroll
        for (int k = 0; k < 16; k++) hcv[k] = __shfl_sync(FULLMASK, hact, 16 + k);
#pragma unroll
        for (int k = 0; k < 16; k++) hvv[k] = __shfl_sync(FULLMASK, hact, k);

        // g rows (4 per lane) and f (meaningful on lanes 0-15; zero weights elsewhere)
        float g0 = tanh_fast(dot16(cw2[0], hcv, cb2r[0]));
        float g1 = tanh_fast(dot16(cw2[1], hcv, cb2r[1]));
        float g2 = tanh_fast(dot16(cw2[2], hcv, cb2r[2]));
        float g3 = tanh_fast(dot16(cw2[3], hcv, cb2r[3]));
        float fv = tanh_fast(dot16(vw2, hvv, vb2r));

        // einsum: lane covers h = lane>>1, d = d0..d0+3
        float part;
        part = g0 * (cv.x - pv.x);
        part = fmaf(g1, cv.y - pv.y, part);
        part = fmaf(g2, cv.z - pv.z, part);
        part = fmaf(g3, cv.w - pv.w, part);
        part += __shfl_xor_sync(FULLMASK, part, 1);       // sum the two d-halves of h
        float fh = __shfl_sync(FULLMASK, fv, lane >> 1);  // f[h] from lane h

        float ynew = yv[lane >> 1] + fh + part;           // valid in lanes 2h, 2h+1
#pragma unroll
        for (int k = 0; k < 16; k++) yv[k] = __shfl_sync(FULLMASK, ynew, 2 * k);
    };

    // ---- main loop: 4-step bodies with register-rotated row prefetch ----
    float4 rA = ldrow(0), rB = ldrow(1), rC = ldrow(2), rD = ldrow(3);
    int n = 0;
#pragma unroll 1
    for (int it = 0; it < 1023; it++) {   // n = 0..4091, prefetch rows n+4..n+7 <= 4095
        float4 p0 = ldrow(n + 4);
        step(rA, rB);
        float4 p1 = ldrow(n + 5);
        step(rB, rC);
        float4 p2 = ldrow(n + 6);
        step(rC, rD);
        float4 p3 = ldrow(n + 7);
        step(rD, p0);
        rA = p0; rB = p1; rC = p2; rD = p3;
        n += 4;
    }
    // tail: n = 4092, 4093, 4094 (rows 4092..4095 already resident)
    step(rA, rB);
    step(rB, rC);
    step(rC, rD);

    // ---- readout of yT ----
    if (lane == 0) {
        float a = rb[0];
#pragma unroll
        for (int k = 0; k < 16; k++) a = fmaf(rW[k], yv[k], a);
        out[b * 2 + 1] = a;
    }
}

extern "C" void kernel_launch(void* const* d_in, const int* in_sizes, int n_in,
                              void* d_out, int out_size) {
    const float* ts  = (const float*)d_in[0];
    const float* ys  = (const float*)d_in[1];
    const float* iW1 = (const float*)d_in[2];
    const float* ib1 = (const float*)d_in[3];
    const float* iW2 = (const float*)d_in[4];
    const float* ib2 = (const float*)d_in[5];
    const float* vW1 = (const float*)d_in[6];
    const float* vb1 = (const float*)d_in[7];
    const float* vW2 = (const float*)d_in[8];
    const float* vb2 = (const float*)d_in[9];
    const float* cW1 = (const float*)d_in[10];
    const float* cb1 = (const float*)d_in[11];
    const float* cW2 = (const float*)d_in[12];
    const float* cb2 = (const float*)d_in[13];
    const float* rW  = (const float*)d_in[14];
    const float* rb  = (const float*)d_in[15];

    const int Bn = out_size / 2;  // (B, 2, 1) float32
    sde_scan_kernel<<<Bn, 32>>>(ts, ys, iW1, ib1, iW2, ib2,
                                vW1, vb1, vW2, vb2,
                                cW1, cb1, cW2, cb2, rW, rb,
                                (float*)d_out);
}

// round 3
// speedup vs baseline: 1.1639x; 1.0736x over previous
#include <cuda_runtime.h>

// Discriminator neural-SDE scan. B=512, T=4096, D=8, H=16, W=16.
// TWO warps per batch element (64-thread blocks, 512 blocks):
//   warp 0: hidden rows 0-15 (vW1) + y outputs h=0..7
//   warp 1: hidden rows 16-31 (cW1) + y outputs h=8..15
// Phase-1 rows K-split across lane pairs; g rows 2/lane; f rows K-split.
// h and y exchanged via SMEM + __syncthreads (2 per step). ycur register-resident.

#define T_STEPS 4096
#define FULLMASK 0xffffffffu

__device__ __forceinline__ float dot16(const float* __restrict__ w,
                                       const float* __restrict__ v,
                                       float init) {
    float a0 = init, a1 = 0.f, a2 = 0.f, a3 = 0.f;
#pragma unroll
    for (int k = 0; k < 16; k += 4) {
        a0 = fmaf(w[k + 0], v[k + 0], a0);
        a1 = fmaf(w[k + 1], v[k + 1], a1);
        a2 = fmaf(w[k + 2], v[k + 2], a2);
        a3 = fmaf(w[k + 3], v[k + 3], a3);
    }
    return (a0 + a1) + (a2 + a3);
}

// tanh(x) = 1 - 2/(exp(2x)+1); EX2-based, branchless, saturates via inf/0.
__device__ __forceinline__ float tanh_fast(float x) {
    float e = __expf(2.f * x);
    return 1.f - __fdividef(2.f, e + 1.f);
}

// lipswish(x) = 0.909 * x * sigmoid(x), EX2-based.
__device__ __forceinline__ float lipswish_fast(float x) {
    return 0.909f * x * __fdividef(1.f, 1.f + __expf(-x));
}

__global__ void __launch_bounds__(64) sde_scan_kernel(
    const float* __restrict__ ts, const float* __restrict__ ys,
    const float* __restrict__ iW1, const float* __restrict__ ib1,
    const float* __restrict__ iW2, const float* __restrict__ ib2,
    const float* __restrict__ vW1, const float* __restrict__ vb1,
    const float* __restrict__ vW2, const float* __restrict__ vb2,
    const float* __restrict__ cW1, const float* __restrict__ cb1,
    const float* __restrict__ cW2, const float* __restrict__ cb2,
    const float* __restrict__ rW, const float* __restrict__ rb,
    float* __restrict__ out)
{
    const int b    = blockIdx.x;
    const int tid  = threadIdx.x;
    const int w    = tid >> 5;        // 0 or 1
    const int lane = tid & 31;
    const int khalf = lane & 1;       // K-split half for phase 1 / f-dot
    const int hloc  = lane >> 2;      // 0..7: local y-output index
    const int dpair = lane & 3;       // 0..3: d-pair for g/einsum
    const int hb    = w * 8;          // y-output base for this warp

    __shared__ __align__(16) float s_y[16];
    __shared__ __align__(16) float s_h[32];

    const float t0 = ts[0];
    const float* __restrict__ ysb = ys + (size_t)b * (T_STEPS * 8);

    // ---- phase-1 weights: hidden row r1 = w*16 + (lane>>1), K-half = khalf ----
    const int r1 = w * 16 + (lane >> 1);
    float w1p[8], wt = 0.f, b1r = 0.f;
    {
        const float* Wrow = (r1 < 16) ? (vW1 + r1 * 17) : (cW1 + (r1 - 16) * 17);
#pragma unroll
        for (int k = 0; k < 8; k++) w1p[k] = Wrow[1 + khalf * 8 + k];
        if (khalf == 0) {
            wt  = Wrow[0];
            b1r = (r1 < 16) ? vb1[r1] : cb1[r1 - 16];
        }
    }

    // ---- g weights: 2 flat rows per lane: flat = (hb+hloc)*8 + 2*dpair (+1) ----
    float cw2a[16], cw2b[16], cb2a, cb2b;
    {
        const int fl0 = (hb + hloc) * 8 + 2 * dpair;
        cb2a = cb2[fl0];
        cb2b = cb2[fl0 + 1];
#pragma unroll
        for (int k = 0; k < 16; k++) {
            cw2a[k] = cW2[fl0 * 16 + k];
            cw2b[k] = cW2[(fl0 + 1) * 16 + k];
        }
    }

    // ---- f weights: rows hb..hb+7, K-split on lanes 0-15; zeros elsewhere ----
    float vw2p[8], fb1 = 0.f;
#pragma unroll
    for (int k = 0; k < 8; k++) vw2p[k] = 0.f;
    if (lane < 16) {
        const int rf = hb + (lane >> 1);
#pragma unroll
        for (int k = 0; k < 8; k++) vw2p[k] = vW2[rf * 16 + khalf * 8 + k];
        if (khalf == 0) fb1 = vb2[rf];
    }

    // ---- initial MLP (warp 0): y0 = relu([t0, ys0] @ iW1^T + ib1) @ iW2^T + ib2 ----
    if (w == 0) {
        float a = 0.f;
        if (lane < 16) {
            a = fmaf(iW1[lane * 9], t0, ib1[lane]);
#pragma unroll
            for (int k = 0; k < 8; k++) a = fmaf(iW1[lane * 9 + 1 + k], ysb[k], a);
            a = fmaxf(a, 0.f);
        }
        float hv[16];
#pragma unroll
        for (int k = 0; k < 16; k++) hv[k] = __shfl_sync(FULLMASK, a, k);
        float y0 = 0.f;
        if (lane < 16) {
            y0 = ib2[lane];
#pragma unroll
            for (int k = 0; k < 16; k++) y0 = fmaf(iW2[lane * 16 + k], hv[k], y0);
            s_y[lane] = y0;
        }
        float yv16[16];
#pragma unroll
        for (int k = 0; k < 16; k++) yv16[k] = __shfl_sync(FULLMASK, y0, k);
        if (lane == 0) {
            float acc = rb[0];
#pragma unroll
            for (int k = 0; k < 16; k++) acc = fmaf(rW[k], yv16[k], acc);
            out[b * 2 + 0] = acc;
        }
    }
    __syncthreads();

    float ycur = s_y[hb + hloc];   // register-resident y[h] (replicated in 4-lane group)
    float tf = t0;

    // ---- dx row loads: per-lane float2 at d = 2*dpair ----
    const int d0e = 2 * dpair;
    auto ldrow = [&](int r) -> float2 {
        return *reinterpret_cast<const float2*>(ysb + (size_t)r * 8 + d0e);
    };

    // ---- one Euler step ----
    auto step = [&](const float2 pv, const float2 cv) {
        // phase 1: h[r1] = lipswish(W1 @ [t, y] + b1), K-split over lane pairs
        const float4* yq = reinterpret_cast<const float4*>(s_y);
        float4 qa = yq[khalf * 2 + 0], qb = yq[khalf * 2 + 1];
        float a = fmaf(wt, tf, b1r);
        a = fmaf(w1p[0], qa.x, a);
        a = fmaf(w1p[1], qa.y, a);
        a = fmaf(w1p[2], qa.z, a);
        a = fmaf(w1p[3], qa.w, a);
        a = fmaf(w1p[4], qb.x, a);
        a = fmaf(w1p[5], qb.y, a);
        a = fmaf(w1p[6], qb.z, a);
        a = fmaf(w1p[7], qb.w, a);
        a += __shfl_xor_sync(FULLMASK, a, 1);
        float h = lipswish_fast(a);
        if (khalf == 0) s_h[r1] = h;
        tf += 1.f;
        __syncthreads();

        // phase 2: g rows (2/lane) from h_c = s_h[16..31]
        const float4* hq = reinterpret_cast<const float4*>(s_h);
        float hc[16];
        {
            float4 c0 = hq[4], c1 = hq[5], c2 = hq[6], c3 = hq[7];
            hc[0]=c0.x;  hc[1]=c0.y;  hc[2]=c0.z;  hc[3]=c0.w;
            hc[4]=c1.x;  hc[5]=c1.y;  hc[6]=c1.z;  hc[7]=c1.w;
            hc[8]=c2.x;  hc[9]=c2.y;  hc[10]=c2.z; hc[11]=c2.w;
            hc[12]=c3.x; hc[13]=c3.y; hc[14]=c3.z; hc[15]=c3.w;
        }
        float g0 = tanh_fast(dot16(cw2a, hc, cb2a));
        float g1 = tanh_fast(dot16(cw2b, hc, cb2b));

        // f rows (K-split, lanes 0-15 meaningful) from h_v = s_h[0..15]
        float4 fa = hq[khalf * 2 + 0], fb = hq[khalf * 2 + 1];
        float fp = fb1;
        fp = fmaf(vw2p[0], fa.x, fp);
        fp = fmaf(vw2p[1], fa.y, fp);
        fp = fmaf(vw2p[2], fa.z, fp);
        fp = fmaf(vw2p[3], fa.w, fp);
        fp = fmaf(vw2p[4], fb.x, fp);
        fp = fmaf(vw2p[5], fb.y, fp);
        fp = fmaf(vw2p[6], fb.z, fp);
        fp = fmaf(vw2p[7], fb.w, fp);
        fp += __shfl_xor_sync(FULLMASK, fp, 1);
        float fv = tanh_fast(fp);
        float fh = __shfl_sync(FULLMASK, fv, hloc * 2);  // f[hb+hloc] lives in lane 2*hloc

        // einsum over this lane's d-pair, reduce across 4-lane group
        float part = (cv.x - pv.x) * g0;
        part = fmaf(cv.y - pv.y, g1, part);
        part += __shfl_xor_sync(FULLMASK, part, 1);
        part += __shfl_xor_sync(FULLMASK, part, 2);

        ycur += fh + part;
        if (dpair == 0) s_y[hb + hloc] = ycur;
        __syncthreads();
    };

    // ---- main loop: 4-step bodies with register-rotated row prefetch ----
    float2 rA = ldrow(0), rB = ldrow(1), rC = ldrow(2), rD = ldrow(3);
    int n = 0;
#pragma unroll 1
    for (int it = 0; it < 1023; it++) {   // n = 0..4091, prefetch rows n+4..n+7 <= 4095
        float2 p0 = ldrow(n + 4);
        step(rA, rB);
        float2 p1 = ldrow(n + 5);
        step(rB, rC);
        float2 p2 = ldrow(n + 6);
        step(rC, rD);
        float2 p3 = ldrow(n + 7);
        step(rD, p0);
        rA = p0; rB = p1; rC = p2; rD = p3;
        n += 4;
    }
    // tail: n = 4092, 4093, 4094 (rows already resident)
    step(rA, rB);
    step(rB, rC);
    step(rC, rD);

    // ---- readout of yT (loop ended with __syncthreads) ----
    if (tid == 0) {
        float acc = rb[0];
#pragma unroll
        for (int k = 0; k < 16; k++) acc = fmaf(rW[k], s_y[k], acc);
        out[b * 2 + 1] = acc;
    }
}

extern "C" void kernel_launch(void* const* d_in, const int* in_sizes, int n_in,
                              void* d_out, int out_size) {
    const float* ts  = (const float*)d_in[0];
    const float* ys  = (const float*)d_in[1];
    const float* iW1 = (const float*)d_in[2];
    const float* ib1 = (const float*)d_in[3];
    const float* iW2 = (const float*)d_in[4];
    const float* ib2 = (const float*)d_in[5];
    const float* vW1 = (const float*)d_in[6];
    const float* vb1 = (const float*)d_in[7];
    const float* vW2 = (const float*)d_in[8];
    const float* vb2 = (const float*)d_in[9];
    const float* cW1 = (const float*)d_in[10];
    const float* cb1 = (const float*)d_in[11];
    const float* cW2 = (const float*)d_in[12];
    const float* cb2 = (const float*)d_in[13];
    const float* rW  = (const float*)d_in[14];
    const float* rb  = (const float*)d_in[15];

    const int Bn = out_size / 2;  // (B, 2, 1) float32
    sde_scan_kernel<<<Bn, 64>>>(ts, ys, iW1, ib1, iW2, ib2,
                                vW1, vb1, vW2, vb2,
                                cW1, cb1, cW2, cb2, rW, rb,
                                (float*)d_out);
}